// round 2
// baseline (speedup 1.0000x reference)
#include <cuda_runtime.h>
#include <math.h>

#define NROWS 8192
#define D     128
#define BM    64
#define BN    64
#define BK    64
#define SST   65   // padded smem stride (floats) to avoid fill-phase full conflicts

// Scratch (device globals: no allocation allowed in kernel_launch)
__device__ float g_f[NROWS * D];     // normalized features
__device__ float g_pos[NROWS];
__device__ float g_neg[NROWS];
__device__ int   g_lab[NROWS];

// ---------------------------------------------------------------------------
// Kernel 1: L2-normalize rows, extract labels (int32 or int64 auto-detect),
//           zero accumulators. One block (128 threads) per row.
// ---------------------------------------------------------------------------
__global__ void __launch_bounds__(128) normalize_kernel(
    const float* __restrict__ feat,
    const int*   __restrict__ lab32)   // raw label buffer, dtype unknown
{
    int row = blockIdx.x;
    int t   = threadIdx.x;

    float v  = feat[row * D + t];
    float ss = v * v;
    #pragma unroll
    for (int o = 16; o > 0; o >>= 1) ss += __shfl_xor_sync(0xffffffffu, ss, o);

    __shared__ float wsum[4];
    if ((t & 31) == 0) wsum[t >> 5] = ss;
    __syncthreads();
    float tot = wsum[0] + wsum[1] + wsum[2] + wsum[3];
    float inv = 1.0f / fmaxf(sqrtf(tot), 1e-8f);

    g_f[row * D + t] = v * inv;

    if (t == 0) {
        g_pos[row] = 0.0f;
        g_neg[row] = 0.0f;
        // int64 detection: labels are in [0,100); if stored as int64 (LE),
        // every odd 32-bit word is 0. For int32 data, P(64 odd words all
        // zero) ~ 1e-128.
        bool is64 = true;
        #pragma unroll 8
        for (int i = 0; i < 64; i++)
            if (lab32[2 * i + 1] != 0) { is64 = false; break; }
        g_lab[row] = is64 ? lab32[2 * row] : lab32[row];
    }
}

// ---------------------------------------------------------------------------
// Kernel 2: fused tiled sim^T GEMM + clip + exp + mask + per-row pos/neg sums.
// 64x64 tile per block, 256 threads, 4x4 microtile, K split into 2 chunks of
// 64 so static smem stays under 48KB. Both tiles stored k-major [k][row].
// ---------------------------------------------------------------------------
__global__ void __launch_bounds__(256) sim_kernel()
{
    __shared__ float As[BK * SST];
    __shared__ float Bs[BK * SST];

    const int tx = threadIdx.x & 15;
    const int ty = threadIdx.x >> 4;
    const int rowBase = blockIdx.y * BM;
    const int colBase = blockIdx.x * BN;

    float acc[4][4] = {};

    const int lrow = threadIdx.x >> 4;   // 0..15
    const int c4   = threadIdx.x & 15;   // k-group 0..15 (4 floats each)

    #pragma unroll 1
    for (int k0 = 0; k0 < D; k0 += BK) {
        // --- fill tiles (transposed store) ---
        #pragma unroll
        for (int r = 0; r < 4; r++) {
            int row = lrow + r * 16;
            float4 a = *(const float4*)&g_f[(rowBase + row) * D + k0 + c4 * 4];
            As[(c4 * 4 + 0) * SST + row] = a.x;
            As[(c4 * 4 + 1) * SST + row] = a.y;
            As[(c4 * 4 + 2) * SST + row] = a.z;
            As[(c4 * 4 + 3) * SST + row] = a.w;
            float4 b = *(const float4*)&g_f[(colBase + row) * D + k0 + c4 * 4];
            Bs[(c4 * 4 + 0) * SST + row] = b.x;
            Bs[(c4 * 4 + 1) * SST + row] = b.y;
            Bs[(c4 * 4 + 2) * SST + row] = b.z;
            Bs[(c4 * 4 + 3) * SST + row] = b.w;
        }
        __syncthreads();

        // --- 4x4 register-tile FFMA mainloop ---
        #pragma unroll 8
        for (int k = 0; k < BK; k++) {
            float a0 = As[k * SST + ty * 4 + 0];
            float a1 = As[k * SST + ty * 4 + 1];
            float a2 = As[k * SST + ty * 4 + 2];
            float a3 = As[k * SST + ty * 4 + 3];
            float b0 = Bs[k * SST + tx * 4 + 0];
            float b1 = Bs[k * SST + tx * 4 + 1];
            float b2 = Bs[k * SST + tx * 4 + 2];
            float b3 = Bs[k * SST + tx * 4 + 3];
            acc[0][0] += a0 * b0; acc[0][1] += a0 * b1;
            acc[0][2] += a0 * b2; acc[0][3] += a0 * b3;
            acc[1][0] += a1 * b0; acc[1][1] += a1 * b1;
            acc[1][2] += a1 * b2; acc[1][3] += a1 * b3;
            acc[2][0] += a2 * b0; acc[2][1] += a2 * b1;
            acc[2][2] += a2 * b2; acc[2][3] += a2 * b3;
            acc[3][0] += a3 * b0; acc[3][1] += a3 * b1;
            acc[3][2] += a3 * b2; acc[3][3] += a3 * b3;
        }
        __syncthreads();
    }

    // --- epilogue: scale, clip, exp, mask, row-partial sums ---
    const float invT = 1.0f / 0.07f;
    int li[4], lj[4];
    #pragma unroll
    for (int i = 0; i < 4; i++) li[i] = g_lab[rowBase + ty * 4 + i];
    #pragma unroll
    for (int j = 0; j < 4; j++) lj[j] = g_lab[colBase + tx * 4 + j];

    float pos[4] = {}, neg[4] = {};
    #pragma unroll
    for (int i = 0; i < 4; i++) {
        int gi = rowBase + ty * 4 + i;
        #pragma unroll
        for (int j = 0; j < 4; j++) {
            int gj = colBase + tx * 4 + j;
            float s = fminf(fmaxf(acc[i][j] * invT, -10.0f), 10.0f);
            float e = __expf(s);
            float keep = (gi != gj) ? 1.0f : 0.0f;   // exclude diagonal
            e *= keep;
            neg[i] += e;
            pos[i] += (li[i] == lj[j]) ? e : 0.0f;
        }
    }

    // butterfly reduce across the 16 tx lanes (xor 1,2,4,8 stays in half-warp)
    #pragma unroll
    for (int i = 0; i < 4; i++) {
        float p = pos[i], n = neg[i];
        #pragma unroll
        for (int o = 1; o < 16; o <<= 1) {
            p += __shfl_xor_sync(0xffffffffu, p, o);
            n += __shfl_xor_sync(0xffffffffu, n, o);
        }
        if (tx == 0) {
            atomicAdd(&g_pos[rowBase + ty * 4 + i], p);
            atomicAdd(&g_neg[rowBase + ty * 4 + i], n);
        }
    }
}

// ---------------------------------------------------------------------------
// Kernel 3: loss_i = log(max(neg,1e-8)) - log(max(pos,1e-8)); mean.
// ---------------------------------------------------------------------------
__global__ void __launch_bounds__(256) loss_kernel(float* __restrict__ out)
{
    int t = threadIdx.x;
    float s = 0.0f;
    for (int i = t; i < NROWS; i += 256) {
        float p = fmaxf(g_pos[i], 1e-8f);
        float n = fmaxf(g_neg[i], 1e-8f);
        s += logf(n) - logf(p);
    }
    __shared__ float red[256];
    red[t] = s;
    __syncthreads();
    #pragma unroll
    for (int o = 128; o > 0; o >>= 1) {
        if (t < o) red[t] += red[t + o];
        __syncthreads();
    }
    if (t == 0) out[0] = red[0] * (1.0f / (float)NROWS);
}

// ---------------------------------------------------------------------------
extern "C" void kernel_launch(void* const* d_in, const int* in_sizes, int n_in,
                              void* d_out, int out_size)
{
    const float* feat  = (const float*)d_in[0];
    const int*   lab32 = (const int*)d_in[1];   // dtype auto-detected on device
    float*       out   = (float*)d_out;

    normalize_kernel<<<NROWS, 128>>>(feat, lab32);
    dim3 grid(NROWS / BN, NROWS / BM);
    sim_kernel<<<grid, 256>>>();
    loss_kernel<<<1, 256>>>(out);
}

// round 4
// speedup vs baseline: 2.9122x; 2.9122x over previous
#include <cuda_runtime.h>
#include <cuda_bf16.h>
#include <cstdint>
#include <math.h>

#define NROWS 8192
#define D     128
#define INV_T (1.0f / 0.07f)

#define STAGES   4
#define CHUNKS   12            // 3 products x 4 k32-chunks
#define ROWPITCH 80            // bytes per smem row (64 data + 16 pad)
#define TILEB    (128 * ROWPITCH)          // 10240 B per matrix chunk
#define STAGEB   (2 * TILEB)               // A + B
#define SMEM_DYN_BYTES (STAGES * STAGEB)   // 81920

// ---------------- device scratch -------------------------------------------
__device__ __nv_bfloat16 g_a[NROWS * 256];   // [row][0:128]=hi, [128:256]=lo
__device__ float g_pos[NROWS];
__device__ float g_neg[NROWS];
__device__ int   g_lab[NROWS];

// ---------------- helpers ---------------------------------------------------
__device__ __forceinline__ uint32_t smem_u32(const void* p) {
    return (uint32_t)__cvta_generic_to_shared(p);
}
__device__ __forceinline__ void cpasync16(uint32_t s, const void* g) {
    asm volatile("cp.async.cg.shared.global [%0], [%1], 16;" :: "r"(s), "l"(g));
}
__device__ __forceinline__ void cp_commit() {
    asm volatile("cp.async.commit_group;" ::: "memory");
}
template <int N>
__device__ __forceinline__ void cp_wait() {
    asm volatile("cp.async.wait_group %0;" :: "n"(N) : "memory");
}
__device__ __forceinline__ void ldmx4(uint32_t* r, uint32_t addr) {
    asm volatile("ldmatrix.sync.aligned.m8n8.x4.shared.b16 {%0,%1,%2,%3}, [%4];"
                 : "=r"(r[0]), "=r"(r[1]), "=r"(r[2]), "=r"(r[3]) : "r"(addr));
}
__device__ __forceinline__ void mma16816(float* c, const uint32_t* a, uint32_t b0, uint32_t b1) {
    asm volatile(
        "mma.sync.aligned.m16n8k16.row.col.f32.bf16.bf16.f32 "
        "{%0,%1,%2,%3}, {%4,%5,%6,%7}, {%8,%9}, {%0,%1,%2,%3};"
        : "+f"(c[0]), "+f"(c[1]), "+f"(c[2]), "+f"(c[3])
        : "r"(a[0]), "r"(a[1]), "r"(a[2]), "r"(a[3]), "r"(b0), "r"(b1));
}

// ---------------------------------------------------------------------------
// Kernel 1: normalize rows -> bf16 hi/lo into g_a; labels; zero accumulators.
// ---------------------------------------------------------------------------
__global__ void __launch_bounds__(128) normalize_kernel(
    const float* __restrict__ feat,
    const int*   __restrict__ lab32)
{
    int row = blockIdx.x;
    int t   = threadIdx.x;

    float v  = feat[row * D + t];
    float ss = v * v;
    #pragma unroll
    for (int o = 16; o > 0; o >>= 1) ss += __shfl_xor_sync(0xffffffffu, ss, o);

    __shared__ float wsum[4];
    if ((t & 31) == 0) wsum[t >> 5] = ss;
    __syncthreads();
    float tot = wsum[0] + wsum[1] + wsum[2] + wsum[3];
    float inv = 1.0f / fmaxf(sqrtf(tot), 1e-8f);

    float f = v * inv;
    __nv_bfloat16 hi = __float2bfloat16_rn(f);
    __nv_bfloat16 lo = __float2bfloat16_rn(f - __bfloat162float(hi));
    g_a[row * 256 + t]       = hi;
    g_a[row * 256 + 128 + t] = lo;

    if (t == 0) {
        g_pos[row] = 0.0f;
        g_neg[row] = 0.0f;
        bool is64 = true;
        #pragma unroll 8
        for (int i = 0; i < 64; i++)
            if (lab32[2 * i + 1] != 0) { is64 = false; break; }
        g_lab[row] = is64 ? lab32[2 * row] : lab32[row];
    }
}

// ---------------------------------------------------------------------------
// Kernel 2: 128x128-tile bf16 mma.sync GEMM (K=384 via hi/lo schedule) with
// fused clip/exp/mask/row-sum epilogue. 256 threads: 8 warps (4 row x 2 col),
// each warp 32x64 via m16n8k16.
// ---------------------------------------------------------------------------
__device__ __forceinline__ void load_chunk(uint32_t stageBase, int chunk,
                                           int aRowBase, int bRowBase, int tid)
{
    const int p  = chunk >> 2;
    const int cc = chunk & 3;
    const int aCol = ((p == 2) ? 128 : 0) + cc * 32;   // element offsets
    const int bCol = ((p == 1) ? 128 : 0) + cc * 32;
    #pragma unroll
    for (int it = 0; it < 2; it++) {
        int idx = tid + it * 256;
        int r   = idx >> 2;
        int c4  = idx & 3;                 // 16B chunk within 64B row
        uint32_t sA = stageBase + r * ROWPITCH + c4 * 16;
        uint32_t sB = sA + TILEB;
        cpasync16(sA, (const char*)&g_a[(aRowBase + r) * 256 + aCol] + c4 * 16);
        cpasync16(sB, (const char*)&g_a[(bRowBase + r) * 256 + bCol] + c4 * 16);
    }
}

__global__ void __launch_bounds__(256) sim_mma_kernel()
{
    extern __shared__ char dsm[];
    __shared__ int labA[128];
    __shared__ int labB[128];

    const uint32_t smBase = smem_u32(dsm);
    const int tid  = threadIdx.x;
    const int warp = tid >> 5;
    const int lane = tid & 31;
    const int warpRow = warp >> 1;       // 0..3
    const int warpCol = warp & 1;        // 0..1
    const int aRowBase = blockIdx.y * 128;
    const int bRowBase = blockIdx.x * 128;

    if (tid < 128) {
        labA[tid] = g_lab[aRowBase + tid];
        labB[tid] = g_lab[bRowBase + tid];
    }

    // prologue: fill STAGES-1 stages
    #pragma unroll
    for (int s = 0; s < STAGES - 1; s++) {
        load_chunk(smBase + s * STAGEB, s, aRowBase, bRowBase, tid);
        cp_commit();
    }

    float acc[2][8][4];
    #pragma unroll
    for (int i = 0; i < 2; i++)
        #pragma unroll
        for (int j = 0; j < 8; j++)
            #pragma unroll
            for (int k = 0; k < 4; k++) acc[i][j][k] = 0.0f;

    // ldmatrix lane-relative byte offsets (within a stage's A / B tile)
    uint32_t aOff[2];
    #pragma unroll
    for (int mi = 0; mi < 2; mi++)
        aOff[mi] = (uint32_t)((warpRow * 32 + mi * 16 + (lane & 15)) * ROWPITCH
                              + ((lane >> 4) * 16));
    uint32_t bOff[4];
    #pragma unroll
    for (int nt = 0; nt < 4; nt++)
        bOff[nt] = (uint32_t)((warpCol * 64 + nt * 16 + (lane & 7) + ((lane & 16) ? 8 : 0))
                              * ROWPITCH + ((lane & 8) ? 16 : 0));

    #pragma unroll 1
    for (int c = 0; c < CHUNKS; c++) {
        cp_wait<STAGES - 2>();
        __syncthreads();

        int nf = c + STAGES - 1;
        if (nf < CHUNKS)
            load_chunk(smBase + (nf % STAGES) * STAGEB, nf, aRowBase, bRowBase, tid);
        cp_commit();

        const uint32_t aS = smBase + (c % STAGES) * STAGEB;
        const uint32_t bS = aS + TILEB;

        #pragma unroll
        for (int k16 = 0; k16 < 2; k16++) {
            uint32_t a[2][4];
            ldmx4(a[0], aS + aOff[0] + k16 * 32);
            ldmx4(a[1], aS + aOff[1] + k16 * 32);
            uint32_t b[4][4];
            #pragma unroll
            for (int nt = 0; nt < 4; nt++)
                ldmx4(b[nt], bS + bOff[nt] + k16 * 32);
            #pragma unroll
            for (int mi = 0; mi < 2; mi++)
                #pragma unroll
                for (int n8 = 0; n8 < 8; n8++) {
                    const uint32_t* bf = b[n8 >> 1];
                    if (n8 & 1) mma16816(acc[mi][n8], a[mi], bf[2], bf[3]);
                    else        mma16816(acc[mi][n8], a[mi], bf[0], bf[1]);
                }
        }
    }

    // ---------------- fused epilogue ----------------
    const int g   = lane >> 2;
    const int tig = lane & 3;

    #pragma unroll
    for (int mi = 0; mi < 2; mi++) {
        #pragma unroll
        for (int h = 0; h < 2; h++) {
            const int rT   = warpRow * 32 + mi * 16 + h * 8 + g;   // row in tile
            const int grow = aRowBase + rT;
            const int lrow = labA[rT];
            float pos = 0.0f, neg = 0.0f;
            #pragma unroll
            for (int n8 = 0; n8 < 8; n8++) {
                #pragma unroll
                for (int e = 0; e < 2; e++) {
                    const int cT = warpCol * 64 + n8 * 8 + 2 * tig + e;
                    float v = acc[mi][n8][h * 2 + e];
                    float s = fminf(fmaxf(v * INV_T, -10.0f), 10.0f);
                    float ex = __expf(s);
                    ex = (grow == bRowBase + cT) ? 0.0f : ex;
                    neg += ex;
                    pos += (lrow == labB[cT]) ? ex : 0.0f;
                }
            }
            #pragma unroll
            for (int o = 1; o < 4; o <<= 1) {
                pos += __shfl_xor_sync(0xffffffffu, pos, o);
                neg += __shfl_xor_sync(0xffffffffu, neg, o);
            }
            if (tig == 0) {
                atomicAdd(&g_pos[grow], pos);
                atomicAdd(&g_neg[grow], neg);
            }
        }
    }
}

// ---------------------------------------------------------------------------
// Kernel 3: final loss reduction.
// ---------------------------------------------------------------------------
__global__ void __launch_bounds__(256) loss_kernel(float* __restrict__ out)
{
    int t = threadIdx.x;
    float s = 0.0f;
    for (int i = t; i < NROWS; i += 256) {
        float p = fmaxf(g_pos[i], 1e-8f);
        float n = fmaxf(g_neg[i], 1e-8f);
        s += logf(n) - logf(p);
    }
    __shared__ float red[256];
    red[t] = s;
    __syncthreads();
    #pragma unroll
    for (int o = 128; o > 0; o >>= 1) {
        if (t < o) red[t] += red[t + o];
        __syncthreads();
    }
    if (t == 0) out[0] = red[0] * (1.0f / (float)NROWS);
}

// ---------------------------------------------------------------------------
extern "C" void kernel_launch(void* const* d_in, const int* in_sizes, int n_in,
                              void* d_out, int out_size)
{
    const float* feat  = (const float*)d_in[0];
    const int*   lab32 = (const int*)d_in[1];
    float*       out   = (float*)d_out;

    static bool attr_set = false;
    if (!attr_set) {
        cudaFuncSetAttribute(sim_mma_kernel, cudaFuncAttributeMaxDynamicSharedMemorySize,
                             SMEM_DYN_BYTES);
        attr_set = true;
    }

    normalize_kernel<<<NROWS, 128>>>(feat, lab32);
    dim3 grid(64, 64);
    sim_mma_kernel<<<grid, 256, SMEM_DYN_BYTES>>>();
    loss_kernel<<<1, 256>>>(out);
}

// round 5
// speedup vs baseline: 4.9763x; 1.7087x over previous
#include <cuda_runtime.h>
#include <cuda_bf16.h>
#include <cstdint>
#include <math.h>

#define NROWS 8192
#define D     128
#define INV_T (1.0f / 0.07f)

#define NT       64            // 8192/128 tile grid dimension
#define NTILES   2080          // NT*(NT+1)/2
#define STAGES   4
#define CHUNKS   12            // 3 products x 4 k32-chunks
#define ROWPITCH 80            // bytes per smem row (64 data + 16 pad)
#define TILEB    (128 * ROWPITCH)
#define STAGEB   (2 * TILEB)
#define SMEM_DYN_BYTES (STAGES * STAGEB)   // 81920

// ---------------- device scratch -------------------------------------------
__device__ __nv_bfloat16 g_a[NROWS * 256];   // [row][0:128]=hi, [128:256]=lo
__device__ float g_pos[NROWS];
__device__ float g_neg[NROWS];
__device__ int   g_lab[NROWS];

// ---------------- helpers ---------------------------------------------------
__device__ __forceinline__ uint32_t smem_u32(const void* p) {
    return (uint32_t)__cvta_generic_to_shared(p);
}
__device__ __forceinline__ void cpasync16(uint32_t s, const void* g) {
    asm volatile("cp.async.cg.shared.global [%0], [%1], 16;" :: "r"(s), "l"(g));
}
__device__ __forceinline__ void cp_commit() {
    asm volatile("cp.async.commit_group;" ::: "memory");
}
template <int N>
__device__ __forceinline__ void cp_wait() {
    asm volatile("cp.async.wait_group %0;" :: "n"(N) : "memory");
}
__device__ __forceinline__ void ldmx4(uint32_t* r, uint32_t addr) {
    asm volatile("ldmatrix.sync.aligned.m8n8.x4.shared.b16 {%0,%1,%2,%3}, [%4];"
                 : "=r"(r[0]), "=r"(r[1]), "=r"(r[2]), "=r"(r[3]) : "r"(addr));
}
__device__ __forceinline__ void mma16816(float* c, const uint32_t* a, uint32_t b0, uint32_t b1) {
    asm volatile(
        "mma.sync.aligned.m16n8k16.row.col.f32.bf16.bf16.f32 "
        "{%0,%1,%2,%3}, {%4,%5,%6,%7}, {%8,%9}, {%0,%1,%2,%3};"
        : "+f"(c[0]), "+f"(c[1]), "+f"(c[2]), "+f"(c[3])
        : "r"(a[0]), "r"(a[1]), "r"(a[2]), "r"(a[3]), "r"(b0), "r"(b1));
}

// ---------------------------------------------------------------------------
// Kernel 1: warp-per-row normalize -> bf16 hi/lo; labels; zero accumulators.
// ---------------------------------------------------------------------------
__global__ void __launch_bounds__(256) normalize_kernel(
    const float* __restrict__ feat,
    const int*   __restrict__ lab32)
{
    const int warp = threadIdx.x >> 5;
    const int lane = threadIdx.x & 31;
    const int row  = blockIdx.x * 8 + warp;

    float4 v = *(const float4*)&feat[row * D + lane * 4];
    float ss = v.x * v.x + v.y * v.y + v.z * v.z + v.w * v.w;
    #pragma unroll
    for (int o = 16; o > 0; o >>= 1) ss += __shfl_xor_sync(0xffffffffu, ss, o);
    float inv = 1.0f / fmaxf(sqrtf(ss), 1e-8f);

    float f[4] = { v.x * inv, v.y * inv, v.z * inv, v.w * inv };
    ushort hi[4], lo[4];
    #pragma unroll
    for (int k = 0; k < 4; k++) {
        __nv_bfloat16 h = __float2bfloat16_rn(f[k]);
        __nv_bfloat16 l = __float2bfloat16_rn(f[k] - __bfloat162float(h));
        hi[k] = __bfloat16_as_ushort(h);
        lo[k] = __bfloat16_as_ushort(l);
    }
    ushort* a16 = (ushort*)g_a;
    *(uint2*)&a16[row * 256 + lane * 4]       = make_uint2(hi[0] | (uint32_t)hi[1] << 16,
                                                           hi[2] | (uint32_t)hi[3] << 16);
    *(uint2*)&a16[row * 256 + 128 + lane * 4] = make_uint2(lo[0] | (uint32_t)lo[1] << 16,
                                                           lo[2] | (uint32_t)lo[3] << 16);

    if (lane == 0) {
        g_pos[row] = 0.0f;
        g_neg[row] = 0.0f;
        bool is64 = true;
        #pragma unroll 8
        for (int i = 0; i < 32; i++)
            if (lab32[2 * i + 1] != 0) { is64 = false; break; }
        g_lab[row] = is64 ? lab32[2 * row] : lab32[row];
    }
}

// ---------------------------------------------------------------------------
// Kernel 2: upper-triangular 128x128 bf16 mma.sync tiles (K=384 hi/lo
// schedule). Off-diagonal tiles feed BOTH row sums (A rows) and column sums
// (B rows) — masks are symmetric. Diagonal tiles: row sums only, minus eye.
// ---------------------------------------------------------------------------
__device__ __forceinline__ void load_chunk(uint32_t stageBase, int chunk,
                                           int aRowBase, int bRowBase, int tid)
{
    const int p  = chunk >> 2;
    const int cc = chunk & 3;
    const int aCol = ((p == 2) ? 128 : 0) + cc * 32;
    const int bCol = ((p == 1) ? 128 : 0) + cc * 32;
    #pragma unroll
    for (int it = 0; it < 2; it++) {
        int idx = tid + it * 256;
        int r   = idx >> 2;
        int c4  = idx & 3;
        uint32_t sA = stageBase + r * ROWPITCH + c4 * 16;
        cpasync16(sA,         (const char*)&g_a[(aRowBase + r) * 256 + aCol] + c4 * 16);
        cpasync16(sA + TILEB, (const char*)&g_a[(bRowBase + r) * 256 + bCol] + c4 * 16);
    }
}

__global__ void __launch_bounds__(256, 2) sim_mma_kernel()
{
    extern __shared__ char dsm[];
    __shared__ int labA[128];
    __shared__ int labB[128];

    const uint32_t smBase = smem_u32(dsm);
    const int tid  = threadIdx.x;
    const int warp = tid >> 5;
    const int lane = tid & 31;
    const int warpRow = warp >> 1;
    const int warpCol = warp & 1;

    // decode linear tile id -> upper-triangular (i, j), i <= j
    int ti = blockIdx.x;
    int i  = (int)floorf((129.0f - sqrtf(129.0f * 129.0f - 8.0f * (float)ti)) * 0.5f);
    while (i > 0 && ti < i * NT - i * (i - 1) / 2) --i;
    while (ti >= (i + 1) * NT - (i + 1) * i / 2) ++i;
    const int j = i + (ti - (i * NT - i * (i - 1) / 2));
    const bool diag = (i == j);
    const int aRowBase = i * 128;
    const int bRowBase = j * 128;

    if (tid < 128) {
        labA[tid] = g_lab[aRowBase + tid];
        labB[tid] = g_lab[bRowBase + tid];
    }

    #pragma unroll
    for (int s = 0; s < STAGES - 1; s++) {
        load_chunk(smBase + s * STAGEB, s, aRowBase, bRowBase, tid);
        cp_commit();
    }

    float acc[2][8][4];
    #pragma unroll
    for (int a = 0; a < 2; a++)
        #pragma unroll
        for (int b = 0; b < 8; b++)
            #pragma unroll
            for (int k = 0; k < 4; k++) acc[a][b][k] = 0.0f;

    uint32_t aOff[2];
    #pragma unroll
    for (int mi = 0; mi < 2; mi++)
        aOff[mi] = (uint32_t)((warpRow * 32 + mi * 16 + (lane & 15)) * ROWPITCH
                              + ((lane >> 4) * 16));
    uint32_t bOff[4];
    #pragma unroll
    for (int nt = 0; nt < 4; nt++)
        bOff[nt] = (uint32_t)((warpCol * 64 + nt * 16 + (lane & 7) + ((lane & 16) ? 8 : 0))
                              * ROWPITCH + ((lane & 8) ? 16 : 0));

    #pragma unroll 1
    for (int c = 0; c < CHUNKS; c++) {
        cp_wait<STAGES - 2>();
        __syncthreads();

        int nf = c + STAGES - 1;
        if (nf < CHUNKS)
            load_chunk(smBase + (nf % STAGES) * STAGEB, nf, aRowBase, bRowBase, tid);
        cp_commit();

        const uint32_t aS = smBase + (c % STAGES) * STAGEB;
        const uint32_t bS = aS + TILEB;

        #pragma unroll
        for (int k16 = 0; k16 < 2; k16++) {
            uint32_t a[2][4];
            ldmx4(a[0], aS + aOff[0] + k16 * 32);
            ldmx4(a[1], aS + aOff[1] + k16 * 32);
            uint32_t b[4][4];
            #pragma unroll
            for (int nt = 0; nt < 4; nt++)
                ldmx4(b[nt], bS + bOff[nt] + k16 * 32);
            #pragma unroll
            for (int mi = 0; mi < 2; mi++)
                #pragma unroll
                for (int n8 = 0; n8 < 8; n8++) {
                    const uint32_t* bf = b[n8 >> 1];
                    if (n8 & 1) mma16816(acc[mi][n8], a[mi], bf[2], bf[3]);
                    else        mma16816(acc[mi][n8], a[mi], bf[0], bf[1]);
                }
        }
    }

    // ---------------- fused epilogue (row + column sums) ----------------
    const int g   = lane >> 2;
    const int tig = lane & 3;

    float colPos[16], colNeg[16];
    #pragma unroll
    for (int x = 0; x < 16; x++) { colPos[x] = 0.0f; colNeg[x] = 0.0f; }

    #pragma unroll
    for (int mi = 0; mi < 2; mi++) {
        #pragma unroll
        for (int h = 0; h < 2; h++) {
            const int rT   = warpRow * 32 + mi * 16 + h * 8 + g;
            const int lrow = labA[rT];
            float rowPos = 0.0f, rowNeg = 0.0f;
            #pragma unroll
            for (int n8 = 0; n8 < 8; n8++) {
                #pragma unroll
                for (int e = 0; e < 2; e++) {
                    const int cT = warpCol * 64 + n8 * 8 + 2 * tig + e;
                    float v = acc[mi][n8][h * 2 + e];
                    float s = fminf(fmaxf(v * INV_T, -10.0f), 10.0f);
                    float ex = __expf(s);
                    if (diag) ex = (rT == cT) ? 0.0f : ex;
                    bool m = (lrow == labB[cT]);
                    rowNeg += ex;
                    rowPos += m ? ex : 0.0f;
                    if (!diag) {
                        colNeg[n8 * 2 + e] += ex;
                        colPos[n8 * 2 + e] += m ? ex : 0.0f;
                    }
                }
            }
            #pragma unroll
            for (int o = 1; o < 4; o <<= 1) {
                rowPos += __shfl_xor_sync(0xffffffffu, rowPos, o);
                rowNeg += __shfl_xor_sync(0xffffffffu, rowNeg, o);
            }
            if (tig == 0) {
                atomicAdd(&g_pos[aRowBase + rT], rowPos);
                atomicAdd(&g_neg[aRowBase + rT], rowNeg);
            }
        }
    }

    if (!diag) {
        #pragma unroll
        for (int x = 0; x < 16; x++) {
            #pragma unroll
            for (int o = 4; o < 32; o <<= 1) {
                colPos[x] += __shfl_xor_sync(0xffffffffu, colPos[x], o);
                colNeg[x] += __shfl_xor_sync(0xffffffffu, colNeg[x], o);
            }
        }
        if (g == 0) {
            #pragma unroll
            for (int x = 0; x < 16; x++) {
                const int cT = warpCol * 64 + (x >> 1) * 8 + 2 * tig + (x & 1);
                atomicAdd(&g_pos[bRowBase + cT], colPos[x]);
                atomicAdd(&g_neg[bRowBase + cT], colNeg[x]);
            }
        }
    }
}

// ---------------------------------------------------------------------------
// Kernel 3: final loss reduction.
// ---------------------------------------------------------------------------
__global__ void __launch_bounds__(256) loss_kernel(float* __restrict__ out)
{
    int t = threadIdx.x;
    float s = 0.0f;
    for (int idx = t; idx < NROWS; idx += 256) {
        float p = fmaxf(g_pos[idx], 1e-8f);
        float n = fmaxf(g_neg[idx], 1e-8f);
        s += logf(n) - logf(p);
    }
    __shared__ float red[256];
    red[t] = s;
    __syncthreads();
    #pragma unroll
    for (int o = 128; o > 0; o >>= 1) {
        if (t < o) red[t] += red[t + o];
        __syncthreads();
    }
    if (t == 0) out[0] = red[0] * (1.0f / (float)NROWS);
}

// ---------------------------------------------------------------------------
extern "C" void kernel_launch(void* const* d_in, const int* in_sizes, int n_in,
                              void* d_out, int out_size)
{
    const float* feat  = (const float*)d_in[0];
    const int*   lab32 = (const int*)d_in[1];
    float*       out   = (float*)d_out;

    static bool attr_set = false;
    if (!attr_set) {
        cudaFuncSetAttribute(sim_mma_kernel, cudaFuncAttributeMaxDynamicSharedMemorySize,
                             SMEM_DYN_BYTES);
        attr_set = true;
    }

    normalize_kernel<<<NROWS / 8, 256>>>(feat, lab32);
    sim_mma_kernel<<<NTILES, 256, SMEM_DYN_BYTES>>>();
    loss_kernel<<<1, 256>>>(out);
}